// round 5
// baseline (speedup 1.0000x reference)
#include <cuda_runtime.h>
#include <cuda_bf16.h>
#include <cstdint>

#define NN    50000
#define EE    640000
#define DINN  128
#define DH    256
#define DOUTK 128

// ===================== scratch =============================================
__device__ int   g_deg[NN];
__device__ float g_invc[NN];
__device__ int   g_rowstart[NN + 1];
__device__ int   g_cursor[NN];
__device__ int   g_csr[EE];
__device__ __align__(256) float g_T[(size_t)NN * DH];
__device__ __align__(256) float g_S[(size_t)NN * DH];

// packed operands: uint2 per k-pair = (bf16x2 hi, bf16x2 lo)
__device__ __align__(256) uint2 gP1[(size_t)NN * 128];
__device__ __align__(256) uint2 gP2[(size_t)NN * 128];

// packed B (weights), [n][kpair] interleaved hi/lo
__device__ __align__(256) uint2 gB1[256 * 128];
__device__ __align__(256) uint2 gBsk[256 * 64];
__device__ __align__(256) uint2 gB2[256 * 256];
__device__ __align__(256) uint2 gB3[256 * 128];

__device__ __forceinline__ const uint2* resolve_bw(int id) {
  switch (id) {
    case 1: return gB1;
    case 2: return gBsk;
    case 3: return gB2;
    default: return gB3;
  }
}

__device__ __forceinline__ uint2 pack_pair(float f0, float f1) {
  __nv_bfloat16 h0 = __float2bfloat16(f0);
  __nv_bfloat16 h1 = __float2bfloat16(f1);
  __nv_bfloat16 l0 = __float2bfloat16(f0 - __bfloat162float(h0));
  __nv_bfloat16 l1 = __float2bfloat16(f1 - __bfloat162float(h1));
  uint2 u;
  u.x = (uint32_t)__bfloat16_as_ushort(h0) | ((uint32_t)__bfloat16_as_ushort(h1) << 16);
  u.y = (uint32_t)__bfloat16_as_ushort(l0) | ((uint32_t)__bfloat16_as_ushort(l1) << 16);
  return u;
}
// exact reconstruct of hi+lo (bf16 bits are fp32 upper halves)
__device__ __forceinline__ float2 unpack_pair(uint32_t hx, uint32_t lx) {
  float h0 = __uint_as_float(hx << 16);
  float h1 = __uint_as_float(hx & 0xFFFF0000u);
  float l0 = __uint_as_float(lx << 16);
  float l1 = __uint_as_float(lx & 0xFFFF0000u);
  return make_float2(h0 + l0, h1 + l1);
}
__device__ __forceinline__ float4 unpack_quad(uint4 u) {
  float2 a = unpack_pair(u.x, u.y);
  float2 b = unpack_pair(u.z, u.w);
  return make_float4(a.x, a.y, b.x, b.y);
}

// ===================== CSR build ===========================================
__global__ void zero_deg_kernel() {
  int i = blockIdx.x * blockDim.x + threadIdx.x;
  if (i < NN) g_deg[i] = 0;
}
__global__ void count_kernel(const int* __restrict__ dst) {
  int e = blockIdx.x * blockDim.x + threadIdx.x;
  if (e < EE) atomicAdd(&g_deg[dst[e]], 1);
}
__global__ void scan_kernel() {
  constexpr int T = 1024;
  constexpr int CHUNK = (NN + T - 1) / T;
  __shared__ int sums[T];
  const int tid = threadIdx.x;
  const int start = tid * CHUNK;
  const int end = (start + CHUNK < NN) ? (start + CHUNK) : NN;
  int s = 0;
  for (int i = start; i < end; ++i) s += g_deg[i];
  sums[tid] = s;
  __syncthreads();
  for (int off = 1; off < T; off <<= 1) {
    int v = 0;
    if (tid >= off) v = sums[tid - off];
    __syncthreads();
    if (tid >= off) sums[tid] += v;
    __syncthreads();
  }
  int run = (tid == 0) ? 0 : sums[tid - 1];
  for (int i = start; i < end; ++i) {
    const int d = g_deg[i];
    g_rowstart[i] = run;
    g_cursor[i]   = run;
    g_invc[i]     = 1.0f / (float)(d > 1 ? d : 1);
    run += d;
  }
  if (end == NN) g_rowstart[NN] = run;
}
__global__ void fill_kernel(const int* __restrict__ src, const int* __restrict__ dst) {
  int e = blockIdx.x * blockDim.x + threadIdx.x;
  if (e < EE) {
    int pos = atomicAdd(&g_cursor[dst[e]], 1);
    g_csr[pos] = src[e];
  }
}

// ===================== pack x ==============================================
__global__ void pack_x_kernel(const float* __restrict__ x) {
  int idx = blockIdx.x * blockDim.x + threadIdx.x;
  if (idx >= NN * 32) return;                // 32 float4 per row (DIN=128)
  float4 v = ((const float4*)x)[idx];
  uint2 p0 = pack_pair(v.x, v.y);
  uint2 p1 = pack_pair(v.z, v.w);
  ((uint4*)gP2)[idx] = make_uint4(p0.x, p0.y, p1.x, p1.y);
}

// ===================== merged weight prep ==================================
__device__ __forceinline__ void prep_one(const float* __restrict__ W, int N,
                                         int Kp, uint2* dst, int KpB, int pOff,
                                         int nOff, int li) {
  int n = li / Kp, p = li % Kp;
  float f0 = W[(size_t)(2 * p) * N + n];
  float f1 = W[(size_t)(2 * p + 1) * N + n];
  dst[(size_t)(nOff + n) * KpB + pOff + p] = pack_pair(f0, f1);
}
__global__ void prep_all(const float* W1l, const float* W1r, const float* Wsk,
                         const float* W2l, const float* W2r, const float* W3l,
                         const float* W3r) {
  int idx = blockIdx.x * blockDim.x + threadIdx.x;
  if (idx < 16384)        prep_one(W1l, 256, 64,  gB1,  128, 0,   0,   idx);
  else if (idx < 32768)   prep_one(W1r, 256, 64,  gB1,  128, 64,  0,   idx - 16384);
  else if (idx < 49152)   prep_one(Wsk, 256, 64,  gBsk, 64,  0,   0,   idx - 32768);
  else if (idx < 81920)   prep_one(W2l, 256, 128, gB2,  256, 0,   0,   idx - 49152);
  else if (idx < 114688)  prep_one(W2r, 256, 128, gB2,  256, 128, 0,   idx - 81920);
  else if (idx < 131072)  prep_one(W3l, 128, 128, gB3,  128, 0,   0,   idx - 114688);
  else if (idx < 147456)  prep_one(W3r, 128, 128, gB3,  128, 0,   128, idx - 131072);
}

// ===================== aggregation kernels =================================
// layer-1: mean over x (fp32, D=128), 1 warp/node, packed output to gP1
__global__ void agg_x_kernel(const float* __restrict__ X) {
  const int warp = (blockIdx.x * blockDim.x + threadIdx.x) >> 5;
  if (warp >= NN) return;
  const int lane = threadIdx.x & 31;
  float4 acc = make_float4(0.f, 0.f, 0.f, 0.f);
  const int beg = g_rowstart[warp];
  const int end = g_rowstart[warp + 1];
  int i = beg;
  for (; i + 8 <= end; i += 8) {
    float4 t[8];
#pragma unroll
    for (int j = 0; j < 8; ++j)
      t[j] = *(const float4*)(X + (size_t)g_csr[i + j] * DINN + lane * 4);
#pragma unroll
    for (int j = 0; j < 8; ++j) {
      acc.x += t[j].x; acc.y += t[j].y; acc.z += t[j].z; acc.w += t[j].w;
    }
  }
  for (; i < end; ++i) {
    float4 t = *(const float4*)(X + (size_t)g_csr[i] * DINN + lane * 4);
    acc.x += t.x; acc.y += t.y; acc.z += t.z; acc.w += t.w;
  }
  const float ic = g_invc[warp];
  uint2 p0 = pack_pair(acc.x * ic, acc.y * ic);
  uint2 p1 = pack_pair(acc.z * ic, acc.w * ic);
  ((uint4*)gP1)[(size_t)warp * 32 + lane] = make_uint4(p0.x, p0.y, p1.x, p1.y);
}

// layer-2: mean over packed h (gP2, D=256), 2 warps/node, packed output gP1
__global__ void agg_h_kernel() {
  const int gw = (blockIdx.x * blockDim.x + threadIdx.x) >> 5;
  if (gw >= 2 * NN) return;
  const int node = gw >> 1;
  const int half = gw & 1;
  const int lane = threadIdx.x & 31;
  const int col = half * 32 + lane;          // uint4 index within 64-wide row
  const uint4* __restrict__ X = (const uint4*)gP2;
  float4 acc = make_float4(0.f, 0.f, 0.f, 0.f);
  const int beg = g_rowstart[node];
  const int end = g_rowstart[node + 1];
  int i = beg;
  for (; i + 8 <= end; i += 8) {
    uint4 u[8];
#pragma unroll
    for (int j = 0; j < 8; ++j) u[j] = X[(size_t)g_csr[i + j] * 64 + col];
#pragma unroll
    for (int j = 0; j < 8; ++j) {
      float4 t = unpack_quad(u[j]);
      acc.x += t.x; acc.y += t.y; acc.z += t.z; acc.w += t.w;
    }
  }
  for (; i < end; ++i) {
    float4 t = unpack_quad(X[(size_t)g_csr[i] * 64 + col]);
    acc.x += t.x; acc.y += t.y; acc.z += t.z; acc.w += t.w;
  }
  const float ic = g_invc[node];
  uint2 p0 = pack_pair(acc.x * ic, acc.y * ic);
  uint2 p1 = pack_pair(acc.z * ic, acc.w * ic);
  ((uint4*)gP1)[(size_t)node * 64 + col] = make_uint4(p0.x, p0.y, p1.x, p1.y);
}

// final layer: out = mean_agg(T[:,0:128]) + T[:,128:256] + b3l
__global__ void agg_final_kernel(const float* __restrict__ b3l,
                                 float* __restrict__ out) {
  const int warp = (blockIdx.x * blockDim.x + threadIdx.x) >> 5;
  if (warp >= NN) return;
  const int lane = threadIdx.x & 31;
  float4 acc = make_float4(0.f, 0.f, 0.f, 0.f);
  const int beg = g_rowstart[warp];
  const int end = g_rowstart[warp + 1];
  int i = beg;
  for (; i + 8 <= end; i += 8) {
    float4 t[8];
#pragma unroll
    for (int j = 0; j < 8; ++j)
      t[j] = *(const float4*)(g_T + (size_t)g_csr[i + j] * DH + lane * 4);
#pragma unroll
    for (int j = 0; j < 8; ++j) {
      acc.x += t[j].x; acc.y += t[j].y; acc.z += t[j].z; acc.w += t[j].w;
    }
  }
  for (; i < end; ++i) {
    float4 t = *(const float4*)(g_T + (size_t)g_csr[i] * DH + lane * 4);
    acc.x += t.x; acc.y += t.y; acc.z += t.z; acc.w += t.w;
  }
  const float ic = g_invc[warp];
  float4 z = *(const float4*)(g_T + (size_t)warp * DH + 128 + lane * 4);
  float4 b = *(const float4*)(b3l + lane * 4);
  float4 r;
  r.x = acc.x * ic + z.x + b.x;
  r.y = acc.y * ic + z.y + b.y;
  r.z = acc.z * ic + z.z + b.z;
  r.w = acc.w * ic + z.w + b.w;
  *(float4*)(out + (size_t)warp * DOUTK + lane * 4) = r;
}

// ===================== SMEM-free bf16 MMA GEMM =============================
__device__ __forceinline__ void mma_bf16(float* d, const uint32_t* a,
                                         const uint32_t* b) {
  asm volatile(
      "mma.sync.aligned.m16n8k16.row.col.f32.bf16.bf16.f32 "
      "{%0,%1,%2,%3}, {%4,%5,%6,%7}, {%8,%9}, {%0,%1,%2,%3};"
      : "+f"(d[0]), "+f"(d[1]), "+f"(d[2]), "+f"(d[3])
      : "r"(a[0]), "r"(a[1]), "r"(a[2]), "r"(a[3]), "r"(b[0]), "r"(b[1]));
}

__global__ void __launch_bounds__(256, 1)
gemm_mma(int a1id, int Kp1, int Kp2, int bid, const float* __restrict__ bias,
         int cid) {
  const int tid = threadIdx.x;
  const int wid = tid >> 5;
  const int lane = tid & 31;
  const int warpM = wid >> 1;
  const int warpN = wid & 1;
  const int rowTile = blockIdx.x * 128;
  const int colTile = blockIdx.y * 128;

  const uint2* __restrict__ A1 = (a1id == 1) ? gP1 : gP2;
  const uint2* __restrict__ A2 = gP2;
  const uint2* __restrict__ B = resolve_bw(bid);
  const int KpB = Kp1 + Kp2;

  const int r0 = lane >> 2;
  const int pq = lane & 3;

  int rowA[2][2];
#pragma unroll
  for (int mt = 0; mt < 2; ++mt) {
    int rb = rowTile + warpM * 32 + mt * 16 + r0;
    rowA[mt][0] = (rb < NN) ? rb : (NN - 1);
    rowA[mt][1] = (rb + 8 < NN) ? (rb + 8) : (NN - 1);
  }
  const uint2* bPtr[8];
#pragma unroll
  for (int nt = 0; nt < 8; ++nt) {
    const int n = colTile + warpN * 64 + nt * 8 + r0;
    bPtr[nt] = B + (size_t)n * KpB + pq;
  }

  float acc[2][8][4];
#pragma unroll
  for (int mt = 0; mt < 2; ++mt)
#pragma unroll
    for (int nt = 0; nt < 8; ++nt)
#pragma unroll
      for (int r = 0; r < 4; ++r) acc[mt][nt][r] = 0.f;

  const int nks = KpB >> 3;
#pragma unroll 2
  for (int ks = 0; ks < nks; ++ks) {
    const int pb = ks * 8;
    const uint2* A;
    int pa, str;
    if (pb < Kp1) { A = A1; pa = pb;       str = Kp1; }
    else          { A = A2; pa = pb - Kp1; str = Kp2; }

    uint2 a[2][4];
#pragma unroll
    for (int mt = 0; mt < 2; ++mt) {
      const uint2* b0 = A + (size_t)rowA[mt][0] * str + pa + pq;
      const uint2* b1 = A + (size_t)rowA[mt][1] * str + pa + pq;
      a[mt][0] = b0[0];
      a[mt][1] = b1[0];
      a[mt][2] = b0[4];
      a[mt][3] = b1[4];
    }
    uint2 b[8][2];
#pragma unroll
    for (int nt = 0; nt < 8; ++nt) {
      const uint2* bb = bPtr[nt] + pb;
      b[nt][0] = bb[0];
      b[nt][1] = bb[4];
    }

    uint32_t ah[2][4], al[2][4], bh[8][2], bl[8][2];
#pragma unroll
    for (int mt = 0; mt < 2; ++mt)
#pragma unroll
      for (int j = 0; j < 4; ++j) { ah[mt][j] = a[mt][j].x; al[mt][j] = a[mt][j].y; }
#pragma unroll
    for (int nt = 0; nt < 8; ++nt)
#pragma unroll
      for (int j = 0; j < 2; ++j) { bh[nt][j] = b[nt][j].x; bl[nt][j] = b[nt][j].y; }

#pragma unroll
    for (int mt = 0; mt < 2; ++mt)
#pragma unroll
      for (int nt = 0; nt < 8; ++nt) mma_bf16(acc[mt][nt], ah[mt], bh[nt]);
#pragma unroll
    for (int mt = 0; mt < 2; ++mt)
#pragma unroll
      for (int nt = 0; nt < 8; ++nt) mma_bf16(acc[mt][nt], ah[mt], bl[nt]);
#pragma unroll
    for (int mt = 0; mt < 2; ++mt)
#pragma unroll
      for (int nt = 0; nt < 8; ++nt) mma_bf16(acc[mt][nt], al[mt], bh[nt]);
  }

  float* __restrict__ C = (cid == 1) ? g_T : g_S;
  const int r0base = rowTile + warpM * 32 + r0;
  const int cbase = colTile + warpN * 64 + pq * 2;
#pragma unroll
  for (int mt = 0; mt < 2; ++mt) {
    const int rr = r0base + mt * 16;
#pragma unroll
    for (int nt = 0; nt < 8; ++nt) {
      const int col = cbase + nt * 8;
      float2 bv = make_float2(0.f, 0.f);
      if (bias) bv = *(const float2*)(bias + col);
      if (rr < NN) {
        float2 v = make_float2(acc[mt][nt][0] + bv.x, acc[mt][nt][1] + bv.y);
        *(float2*)(C + (size_t)rr * 256 + col) = v;
      }
      if (rr + 8 < NN) {
        float2 v = make_float2(acc[mt][nt][2] + bv.x, acc[mt][nt][3] + bv.y);
        *(float2*)(C + (size_t)(rr + 8) * 256 + col) = v;
      }
    }
  }
}

// ===================== LayerNorm + ReLU + skip (packed in/out) =============
// layer==1: skip = g_S (fp32);  layer==2: skip = gP2 (packed, reconstruct)
// output: packed gP2 only
__global__ void ln_kernel(const float* __restrict__ gamma,
                          const float* __restrict__ beta, int layer) {
  const int row = (blockIdx.x * blockDim.x + threadIdx.x) >> 5;
  if (row >= NN) return;
  const int lane = threadIdx.x & 31;
  const float4* t4 = (const float4*)(g_T + (size_t)row * DH);
  float4 v0 = t4[lane];
  float4 v1 = t4[lane + 32];
  float sum = v0.x + v0.y + v0.z + v0.w + v1.x + v1.y + v1.z + v1.w;
  float sq = v0.x * v0.x + v0.y * v0.y + v0.z * v0.z + v0.w * v0.w +
             v1.x * v1.x + v1.y * v1.y + v1.z * v1.z + v1.w * v1.w;
#pragma unroll
  for (int off = 16; off > 0; off >>= 1) {
    sum += __shfl_xor_sync(0xffffffffu, sum, off);
    sq  += __shfl_xor_sync(0xffffffffu, sq, off);
  }
  const float mu = sum * (1.0f / DH);
  const float var = sq * (1.0f / DH) - mu * mu;
  const float rs = rsqrtf(var + 1e-5f);

  uint4* p4 = (uint4*)gP2 + (size_t)row * 64;
  float4 sv0, sv1;
  if (layer == 1) {
    const float4* s4 = (const float4*)(g_S + (size_t)row * DH);
    sv0 = s4[lane];
    sv1 = s4[lane + 32];
  } else {
    sv0 = unpack_quad(p4[lane]);
    sv1 = unpack_quad(p4[lane + 32]);
  }
  const float4* g4 = (const float4*)gamma;
  const float4* b4 = (const float4*)beta;
#pragma unroll
  for (int v = 0; v < 2; ++v) {
    float4 tv = (v == 0) ? v0 : v1;
    float4 sv = (v == 0) ? sv0 : sv1;
    float4 gv = g4[lane + 32 * v];
    float4 bv = b4[lane + 32 * v];
    float4 r;
    r.x = fmaxf(0.f, (tv.x - mu) * rs * gv.x + bv.x) + sv.x;
    r.y = fmaxf(0.f, (tv.y - mu) * rs * gv.y + bv.y) + sv.y;
    r.z = fmaxf(0.f, (tv.z - mu) * rs * gv.z + bv.z) + sv.z;
    r.w = fmaxf(0.f, (tv.w - mu) * rs * gv.w + bv.w) + sv.w;
    uint2 q0 = pack_pair(r.x, r.y);
    uint2 q1 = pack_pair(r.z, r.w);
    p4[lane + 32 * v] = make_uint4(q0.x, q0.y, q1.x, q1.y);
  }
}

// ===================== launch ==============================================
extern "C" void kernel_launch(void* const* d_in, const int* in_sizes, int n_in,
                              void* d_out, int out_size) {
  const float* x   = (const float*)d_in[0];
  const int*   ei  = (const int*)d_in[1];
  const float* W1l = (const float*)d_in[2];
  const float* b1l = (const float*)d_in[3];
  const float* W1r = (const float*)d_in[4];
  const float* g1  = (const float*)d_in[5];
  const float* be1 = (const float*)d_in[6];
  const float* Wsk = (const float*)d_in[7];
  const float* bsk = (const float*)d_in[8];
  const float* W2l = (const float*)d_in[9];
  const float* b2l = (const float*)d_in[10];
  const float* W2r = (const float*)d_in[11];
  const float* g2  = (const float*)d_in[12];
  const float* be2 = (const float*)d_in[13];
  const float* W3l = (const float*)d_in[14];
  const float* b3l = (const float*)d_in[15];
  const float* W3r = (const float*)d_in[16];
  float* out = (float*)d_out;

  const int* src = ei;
  const int* dst = ei + EE;

  const int nodeBlocks = (NN + 255) / 256;
  const int edgeBlocks = (EE + 255) / 256;
  const int warpBlocks = (NN + 7) / 8;        // 1 warp/node kernels
  const int warp2Blocks = (2 * NN + 7) / 8;   // 2 warps/node kernels
  const dim3 gemmGrid((NN + 127) / 128, 2);

  // #1 pack x ; #2 prep weights ; #3 zero deg ; #4 GEMM (profiled slot)
  pack_x_kernel<<<(NN * 32 + 255) / 256, 256>>>(x);
  prep_all<<<(147456 + 255) / 256, 256>>>(W1l, W1r, Wsk, W2l, W2r, W3l, W3r);
  zero_deg_kernel<<<nodeBlocks, 256>>>();
  gemm_mma<<<gemmGrid, 256>>>(2, 64, 0, 2, bsk, 2);     // S = x@Wsk + bsk

  // CSR build
  count_kernel<<<edgeBlocks, 256>>>(dst);
  scan_kernel<<<1, 1024>>>();
  fill_kernel<<<edgeBlocks, 256>>>(src, dst);

  // ---- layer 1: T = [agg(x)|x] @ [W1l;W1r] + b1l ; H = relu(LN(T)) + S
  agg_x_kernel<<<warpBlocks, 256>>>(x);
  gemm_mma<<<gemmGrid, 256>>>(1, 64, 64, 1, b1l, 1);
  ln_kernel<<<warpBlocks, 256>>>(g1, be1, 1);

  // ---- layer 2: T = [agg(H)|H] @ [W2l;W2r] + b2l ; H2 = relu(LN(T)) + H
  agg_h_kernel<<<warp2Blocks, 256>>>();
  gemm_mma<<<gemmGrid, 256>>>(1, 128, 128, 3, b2l, 1);
  ln_kernel<<<warpBlocks, 256>>>(g2, be2, 2);

  // ---- layer 3: T = H2 @ [W3l|W3r] ; out = mean_agg(T[:,:128]) + T[:,128:] + b3l
  gemm_mma<<<gemmGrid, 256>>>(2, 128, 0, 4, nullptr, 1);
  agg_final_kernel<<<warpBlocks, 256>>>(b3l, out);
}